// round 10
// baseline (speedup 1.0000x reference)
#include <cuda_runtime.h>
#include <cuda_fp16.h>
#include <cstdint>
#include <math.h>

#define CHN 256
#define TDIM 4096
#define BATCH 16
#define SKIPOFF ((size_t)BATCH*CHN*TDIM)

// single fp16 planes (device globals: allocation-free)
__device__ __half g_x[(size_t)BATCH*4104*CHN];
__device__ __half g_z[(size_t)BATCH*TDIM*CHN];
__device__ __half g_w1[4*128*512];
__device__ __half g_w2[4*128*256];

// stage: A 64 rows x 80B | B 128 rows x 80B
#define ASTG 5120
#define STG  15360
#define NSTG 3
#define SMEM_SZ 46080   // 3 stages; C staging (128*68*4=34816) reuses region

// ---------------- helpers ----------------
__device__ __forceinline__ uint32_t smem_u32(const void* p) {
    uint32_t a; asm("{ .reg .u64 t; cvta.to.shared.u64 t, %1; cvt.u32.u64 %0, t; }" : "=r"(a) : "l"(p));
    return a;
}
__device__ __forceinline__ void cp16(uint32_t d, const void* s) {
    asm volatile("cp.async.cg.shared.global [%0], [%1], 16;" :: "r"(d), "l"(s));
}
__device__ __forceinline__ void ldmx4(uint32_t* r, uint32_t a) {
    asm volatile("ldmatrix.sync.aligned.m8n8.x4.shared.b16 {%0,%1,%2,%3}, [%4];"
        : "=r"(r[0]), "=r"(r[1]), "=r"(r[2]), "=r"(r[3]) : "r"(a));
}
__device__ __forceinline__ void mma_h(float* d, const uint32_t* a, const uint32_t* b) {
    asm volatile("mma.sync.aligned.m16n8k16.row.col.f32.f16.f16.f32 "
        "{%0,%1,%2,%3}, {%4,%5,%6,%7}, {%8,%9}, {%0,%1,%2,%3};"
        : "+f"(d[0]), "+f"(d[1]), "+f"(d[2]), "+f"(d[3])
        : "r"(a[0]), "r"(a[1]), "r"(a[2]), "r"(a[3]), "r"(b[0]), "r"(b[1]));
}
__device__ __forceinline__ float gatedact(float f, float g) {
    float ef = __expf(2.0f * f);
    float tf = __fdividef(ef - 1.0f, ef + 1.0f);
    float sg = __fdividef(1.0f, 1.0f + __expf(-g));
    return tf * sg;
}

// ---------------------------------------------------------------------------
// Weights: g_w1[nb][n'][k]: n'<64 filter ch nb*64+n', n'>=64 gate;
//   k<256 -> tap1 (pairs x[t]), k>=256 -> tap0 (pairs x[t-8]).
// g_w2[nb][n'][k]: n'<64 res, else skip.
// ---------------------------------------------------------------------------
__global__ void pack_w_kernel(const float* __restrict__ wf, const float* __restrict__ wg,
                              const float* __restrict__ wr, const float* __restrict__ wsk)
{
    int idx = blockIdx.x * blockDim.x + threadIdx.x;
    if (idx < 262144) {
        int nb = idx >> 16, np = (idx >> 9) & 127, k = idx & 511;
        int o = nb * 64 + (np & 63), c = k & 255;
        const float* w = (np < 64) ? wf : wg;
        g_w1[idx] = __float2half_rn(w[o * 512 + c * 2 + ((k < 256) ? 1 : 0)]);
    } else if (idx < 393216) {
        int j = idx - 262144;
        int nb = j >> 15, np = (j >> 8) & 127, k = j & 255;
        int o = nb * 64 + (np & 63);
        g_w2[j] = __float2half_rn((np < 64) ? wr[o * 256 + k] : wsk[o * 256 + k]);
    }
}

// ---------------------------------------------------------------------------
// x -> [b][r=t+8][256] fp16 plane (rows 0-7 zero). grid(64,4,16).
// ---------------------------------------------------------------------------
__global__ void pack_x_kernel(const float* __restrict__ x)
{
    __shared__ float st[64][65];
    int tc = blockIdx.x, cc = blockIdx.y, b = blockIdx.z, tid = threadIdx.x;
    for (int i = tid; i < 64 * 16; i += 256) {
        int c = i >> 4, q = i & 15;
        float4 v = *(const float4*)(x + ((size_t)(b * CHN + cc * 64 + c)) * TDIM + tc * 64 + q * 4);
        st[q*4+0][c] = v.x; st[q*4+1][c] = v.y; st[q*4+2][c] = v.z; st[q*4+3][c] = v.w;
    }
    __syncthreads();
    for (int i = tid; i < 64 * 32; i += 256) {
        int r = i >> 5, cp = (i & 31) * 2;
        __half h0 = __float2half_rn(st[r][cp]), h1 = __float2half_rn(st[r][cp + 1]);
        size_t go = ((size_t)b * 4104 + tc * 64 + 8 + r) * CHN + cc * 64 + cp;
        *(uint32_t*)(g_x + go) = ((uint32_t)__half_as_ushort(h1) << 16) | __half_as_ushort(h0);
    }
    if (tc == 0)
        for (int i = tid; i < 8 * 32; i += 256) {
            int r = i >> 5, cp = (i & 31) * 2;
            *(uint32_t*)(g_x + ((size_t)b * 4104 + r) * CHN + cc * 64 + cp) = 0;
        }
}

// ---------------------------------------------------------------------------
// GEMM: C[64 t][128 n] = A[t][K] * B[n][K]^T, single-pass fp16.
// PHASE 1: A=x image, K=512, epilogue tanh*sigmoid -> z plane.
// PHASE 2: A=z plane, K=256, epilogue bias (+x for res) -> out.
// 8 warps (2m x 4n), warp tile 32x32, 3-stage ring, 4 CTAs/SM.
// ---------------------------------------------------------------------------
template<int PHASE>
__global__ void __launch_bounds__(256, 4) gemm_tc(
    const float* __restrict__ x, const float* __restrict__ b0v,
    const float* __restrict__ b1v, float* __restrict__ out)
{
    extern __shared__ unsigned char smraw[];
    const uint32_t sb = smem_u32(smraw);
    const int tid = threadIdx.x, lane = tid & 31, wid = tid >> 5;
    const int wm = wid & 1, wn = wid >> 1;
    const int tt = blockIdx.x, nb = blockIdx.y, b = blockIdx.z;
    const int t0 = tt * 64;
    const int NK  = (PHASE == 1) ? 16 : 8;
    const int KST = (PHASE == 1) ? 512 : 256;

    const __half* Ap = (PHASE == 1) ? g_x + (size_t)b * 4104 * CHN
                                    : g_z + (size_t)b * TDIM * CHN;
    const __half* Bw = (PHASE == 1) ? g_w1 + nb * 128 * 512 : g_w2 + nb * 128 * 256;

    float acc[2][4][4];
    #pragma unroll
    for (int mi = 0; mi < 2; mi++)
        #pragma unroll
        for (int ni = 0; ni < 4; ni++)
            #pragma unroll
            for (int j = 0; j < 4; j++) acc[mi][ni][j] = 0.0f;

    auto load_stage = [&](int kc, int stg) {
        int koff = (PHASE == 1 && kc < 8) ? 8 : 0;
        int acol = (PHASE == 1) ? (kc & 7) * 32 : kc * 32;
        uint32_t sbase = sb + stg * STG;
        #pragma unroll
        for (int i = 0; i < 3; i++) {
            int idx = tid + i * 256;
            if (idx < 256) {
                int r = idx >> 2, seg = idx & 3;
                const __half* asrc = Ap + (size_t)(t0 + r + koff) * CHN + acol + seg * 8;
                cp16(sbase + r * 80 + seg * 16, asrc);
            } else {
                int j = idx - 256;
                int r = j >> 2, seg = j & 3;
                const __half* bsrc = Bw + (size_t)r * KST + kc * 32 + seg * 8;
                cp16(sbase + ASTG + r * 80 + seg * 16, bsrc);
            }
        }
        asm volatile("cp.async.commit_group;" ::: "memory");
    };

    load_stage(0, 0);
    load_stage(1, 1);

    int stg = 0;
    for (int kc = 0; kc < NK; kc++) {
        if (kc < NK - 1) asm volatile("cp.async.wait_group 1;" ::: "memory");
        else             asm volatile("cp.async.wait_group 0;" ::: "memory");
        __syncthreads();

        // prefetch stage kc+2 into slot freed at iter kc-1 (safe post-barrier)
        if (kc + 2 < NK) {
            int nstg = stg + 2; if (nstg >= NSTG) nstg -= NSTG;
            load_stage(kc + 2, nstg);
        }

        const uint32_t abase = sb + stg * STG;
        const uint32_t bbase = abase + ASTG;
        #pragma unroll
        for (int ks = 0; ks < 2; ks++) {
            uint32_t ah[2][4], bf2[4][2];
            const int arow = lane & 15, acoll = ks * 16 + (lane >> 4) * 8;
            const int brow = (lane & 7) + ((lane >> 4) << 3);
            const int bcol = ks * 16 + ((lane >> 3) & 1) * 8;
            #pragma unroll
            for (int ni2 = 0; ni2 < 2; ni2++) {
                uint32_t t4[4];
                ldmx4(t4, bbase + (wn * 32 + ni2 * 16 + brow) * 80 + bcol * 2);
                bf2[ni2*2][0] = t4[0]; bf2[ni2*2][1] = t4[1];
                bf2[ni2*2+1][0] = t4[2]; bf2[ni2*2+1][1] = t4[3];
            }
            #pragma unroll
            for (int mi = 0; mi < 2; mi++)
                ldmx4(ah[mi], abase + (wm * 32 + mi * 16 + arow) * 80 + acoll * 2);
            #pragma unroll
            for (int mi = 0; mi < 2; mi++)
                #pragma unroll
                for (int ni = 0; ni < 4; ni++)
                    mma_h(acc[mi][ni], ah[mi], bf2[ni]);
        }
        stg++; if (stg >= NSTG) stg = 0;
    }
    __syncthreads();

    // ---- stage C through smem [128 n][68 m] ----
    float* Cs = (float*)smraw;
    {
        const int tr = lane >> 2, tc4 = (lane & 3) * 2;
        #pragma unroll
        for (int mi = 0; mi < 2; mi++)
            #pragma unroll
            for (int ni = 0; ni < 4; ni++) {
                int n0 = wn * 32 + ni * 8 + tc4;
                int m0 = wm * 32 + mi * 16 + tr;
                Cs[n0 * 68 + m0]          = acc[mi][ni][0];
                Cs[(n0 + 1) * 68 + m0]    = acc[mi][ni][1];
                Cs[n0 * 68 + m0 + 8]      = acc[mi][ni][2];
                Cs[(n0 + 1) * 68 + m0 + 8] = acc[mi][ni][3];
            }
    }
    __syncthreads();

    if (PHASE == 1) {
        for (int i = tid; i < 64 * 32; i += 256) {
            int m = i >> 5, cp = (i & 31) * 2;
            float f0 = Cs[cp * 68 + m]        + __ldg(b0v + nb * 64 + cp);
            float f1 = Cs[(cp + 1) * 68 + m]  + __ldg(b0v + nb * 64 + cp + 1);
            float g0 = Cs[(64 + cp) * 68 + m] + __ldg(b1v + nb * 64 + cp);
            float g1 = Cs[(65 + cp) * 68 + m] + __ldg(b1v + nb * 64 + cp + 1);
            __half h0 = __float2half_rn(gatedact(f0, g0));
            __half h1 = __float2half_rn(gatedact(f1, g1));
            size_t go = ((size_t)(b * TDIM + t0 + m)) * CHN + nb * 64 + cp;
            *(uint32_t*)(g_z + go) = ((uint32_t)__half_as_ushort(h1) << 16) | __half_as_ushort(h0);
        }
    } else {
        for (int i = tid; i < 128 * 16; i += 256) {
            int c1 = i >> 4, mp = (i & 15) * 4;
            size_t go = ((size_t)(b * CHN + nb * 64 + ((c1 < 64) ? c1 : c1 - 64))) * TDIM + t0 + mp;
            if (c1 < 64) {
                float bias = __ldg(b0v + nb * 64 + c1);
                float4 xv = *(const float4*)(x + go);
                float4 v = make_float4(Cs[c1*68+mp]   + bias + xv.x,
                                       Cs[c1*68+mp+1] + bias + xv.y,
                                       Cs[c1*68+mp+2] + bias + xv.z,
                                       Cs[c1*68+mp+3] + bias + xv.w);
                *(float4*)(out + go) = v;
            } else {
                float bias = __ldg(b1v + nb * 64 + (c1 - 64));
                float4 v = make_float4(Cs[c1*68+mp]   + bias,
                                       Cs[c1*68+mp+1] + bias,
                                       Cs[c1*68+mp+2] + bias,
                                       Cs[c1*68+mp+3] + bias);
                *(float4*)(out + SKIPOFF + go) = v;
            }
        }
    }
}

// ---------------------------------------------------------------------------
extern "C" void kernel_launch(void* const* d_in, const int* in_sizes, int n_in,
                              void* d_out, int out_size)
{
    const float* x   = (const float*)d_in[0];
    const float* wf  = (const float*)d_in[1];
    const float* bf  = (const float*)d_in[2];
    const float* wg  = (const float*)d_in[3];
    const float* bg  = (const float*)d_in[4];
    const float* wr  = (const float*)d_in[5];
    const float* br  = (const float*)d_in[6];
    const float* wsk = (const float*)d_in[7];
    const float* bsk = (const float*)d_in[8];
    float* out = (float*)d_out;

    cudaFuncSetAttribute(gemm_tc<1>, cudaFuncAttributeMaxDynamicSharedMemorySize, SMEM_SZ);
    cudaFuncSetAttribute(gemm_tc<2>, cudaFuncAttributeMaxDynamicSharedMemorySize, SMEM_SZ);

    pack_w_kernel<<<1536, 256>>>(wf, wg, wr, wsk);
    pack_x_kernel<<<dim3(64, 4, BATCH), 256>>>(x);
    dim3 grid(64, 4, BATCH);
    gemm_tc<1><<<grid, 256, SMEM_SZ>>>(x, bf, bg, out);
    gemm_tc<2><<<grid, 256, SMEM_SZ>>>(x, br, bsk, out);
}

// round 11
// speedup vs baseline: 1.1647x; 1.1647x over previous
#include <cuda_runtime.h>
#include <cuda_fp16.h>
#include <cstdint>
#include <math.h>

#define CHN 256
#define TDIM 4096
#define BATCH 16
#define SKIPOFF ((size_t)BATCH*CHN*TDIM)

// single fp16 planes (device globals: allocation-free)
__device__ __half g_x[(size_t)BATCH*4104*CHN];
__device__ __half g_z[(size_t)BATCH*TDIM*CHN];
__device__ __half g_w1[4*128*512];
__device__ __half g_w2[4*128*256];

// stage: A 64 rows x 80B | B 128 rows x 80B
#define ASTG 5120
#define STG  15360
#define NSTG 4
#define SMEM_SZ 61440   // 4 stages; phase2 C staging (128*68*4=34816) reuses region

// ---------------- helpers ----------------
__device__ __forceinline__ uint32_t smem_u32(const void* p) {
    uint32_t a; asm("{ .reg .u64 t; cvta.to.shared.u64 t, %1; cvt.u32.u64 %0, t; }" : "=r"(a) : "l"(p));
    return a;
}
__device__ __forceinline__ void cp16(uint32_t d, const void* s) {
    asm volatile("cp.async.cg.shared.global [%0], [%1], 16;" :: "r"(d), "l"(s));
}
__device__ __forceinline__ void ldmx4(uint32_t* r, uint32_t a) {
    asm volatile("ldmatrix.sync.aligned.m8n8.x4.shared.b16 {%0,%1,%2,%3}, [%4];"
        : "=r"(r[0]), "=r"(r[1]), "=r"(r[2]), "=r"(r[3]) : "r"(a));
}
__device__ __forceinline__ void mma_h(float* d, const uint32_t* a, const uint32_t* b) {
    asm volatile("mma.sync.aligned.m16n8k16.row.col.f32.f16.f16.f32 "
        "{%0,%1,%2,%3}, {%4,%5,%6,%7}, {%8,%9}, {%0,%1,%2,%3};"
        : "+f"(d[0]), "+f"(d[1]), "+f"(d[2]), "+f"(d[3])
        : "r"(a[0]), "r"(a[1]), "r"(a[2]), "r"(a[3]), "r"(b[0]), "r"(b[1]));
}
__device__ __forceinline__ float gatedact(float f, float g) {
    float ef = __expf(2.0f * f);
    float tf = __fdividef(ef - 1.0f, ef + 1.0f);
    float sg = __fdividef(1.0f, 1.0f + __expf(-g));
    return tf * sg;
}

// ---------------------------------------------------------------------------
// Weights: g_w1[nb][n'][k]: n'<64 filter ch nb*64+n', n'>=64 gate;
//   k<256 -> tap1 (pairs x[t]), k>=256 -> tap0 (pairs x[t-8]).
// g_w2[nb][n'][k]: n'<64 res, else skip.
// ---------------------------------------------------------------------------
__global__ void pack_w_kernel(const float* __restrict__ wf, const float* __restrict__ wg,
                              const float* __restrict__ wr, const float* __restrict__ wsk)
{
    int idx = blockIdx.x * blockDim.x + threadIdx.x;
    if (idx < 262144) {
        int nb = idx >> 16, np = (idx >> 9) & 127, k = idx & 511;
        int o = nb * 64 + (np & 63), c = k & 255;
        const float* w = (np < 64) ? wf : wg;
        g_w1[idx] = __float2half_rn(w[o * 512 + c * 2 + ((k < 256) ? 1 : 0)]);
    } else if (idx < 393216) {
        int j = idx - 262144;
        int nb = j >> 15, np = (j >> 8) & 127, k = j & 255;
        int o = nb * 64 + (np & 63);
        g_w2[j] = __float2half_rn((np < 64) ? wr[o * 256 + k] : wsk[o * 256 + k]);
    }
}

// ---------------------------------------------------------------------------
// x -> [b][r=t+8][256] fp16 plane (rows 0-7 zero). grid(64,4,16).
// ---------------------------------------------------------------------------
__global__ void pack_x_kernel(const float* __restrict__ x)
{
    __shared__ float st[64][65];
    int tc = blockIdx.x, cc = blockIdx.y, b = blockIdx.z, tid = threadIdx.x;
    for (int i = tid; i < 64 * 16; i += 256) {
        int c = i >> 4, q = i & 15;
        float4 v = *(const float4*)(x + ((size_t)(b * CHN + cc * 64 + c)) * TDIM + tc * 64 + q * 4);
        st[q*4+0][c] = v.x; st[q*4+1][c] = v.y; st[q*4+2][c] = v.z; st[q*4+3][c] = v.w;
    }
    __syncthreads();
    for (int i = tid; i < 64 * 32; i += 256) {
        int r = i >> 5, cp = (i & 31) * 2;
        __half h0 = __float2half_rn(st[r][cp]), h1 = __float2half_rn(st[r][cp + 1]);
        size_t go = ((size_t)b * 4104 + tc * 64 + 8 + r) * CHN + cc * 64 + cp;
        *(uint32_t*)(g_x + go) = ((uint32_t)__half_as_ushort(h1) << 16) | __half_as_ushort(h0);
    }
    if (tc == 0)
        for (int i = tid; i < 8 * 32; i += 256) {
            int r = i >> 5, cp = (i & 31) * 2;
            *(uint32_t*)(g_x + ((size_t)b * 4104 + r) * CHN + cc * 64 + cp) = 0;
        }
}

// ---------------------------------------------------------------------------
// GEMM: C[64 t][128 n] = A[t][K] * B[n][K]^T, single-pass fp16.
// PHASE 1: B n-tiles interleaved {f c, f c+8, g c, g c+8} -> in-register f/g
//   pairing, activation straight from accumulators, direct z stores (no Cs).
// PHASE 2: standard mapping + smem C transpose staging (t-major output).
// 8 warps (2m x 4n), warp tile 32x32, 4-stage ring, 3 CTAs/SM.
// ---------------------------------------------------------------------------
template<int PHASE>
__global__ void __launch_bounds__(256, 3) gemm_tc(
    const float* __restrict__ x, const float* __restrict__ b0v,
    const float* __restrict__ b1v, float* __restrict__ out)
{
    extern __shared__ unsigned char smraw[];
    const uint32_t sb = smem_u32(smraw);
    const int tid = threadIdx.x, lane = tid & 31, wid = tid >> 5;
    const int wm = wid & 1, wn = wid >> 1;
    const int tt = blockIdx.x, nb = blockIdx.y, b = blockIdx.z;
    const int t0 = tt * 64;
    const int NK  = (PHASE == 1) ? 16 : 8;
    const int KST = (PHASE == 1) ? 512 : 256;

    const __half* Ap = (PHASE == 1) ? g_x + (size_t)b * 4104 * CHN
                                    : g_z + (size_t)b * TDIM * CHN;
    const __half* Bw = (PHASE == 1) ? g_w1 + nb * 128 * 512 : g_w2 + nb * 128 * 256;

    float acc[2][4][4];
    #pragma unroll
    for (int mi = 0; mi < 2; mi++)
        #pragma unroll
        for (int ni = 0; ni < 4; ni++)
            #pragma unroll
            for (int j = 0; j < 4; j++) acc[mi][ni][j] = 0.0f;

    auto load_stage = [&](int kc, int stg) {
        int koff = (PHASE == 1 && kc < 8) ? 8 : 0;
        int acol = (PHASE == 1) ? (kc & 7) * 32 : kc * 32;
        uint32_t sbase = sb + stg * STG;
        #pragma unroll
        for (int i = 0; i < 3; i++) {
            int idx = tid + i * 256;
            if (idx < 256) {
                int r = idx >> 2, seg = idx & 3;
                const __half* asrc = Ap + (size_t)(t0 + r + koff) * CHN + acol + seg * 8;
                cp16(sbase + r * 80 + seg * 16, asrc);
            } else {
                int j = idx - 256;
                int r = j >> 2, seg = j & 3;
                const __half* bsrc = Bw + (size_t)r * KST + kc * 32 + seg * 8;
                cp16(sbase + ASTG + r * 80 + seg * 16, bsrc);
            }
        }
        asm volatile("cp.async.commit_group;" ::: "memory");
    };

    load_stage(0, 0);
    load_stage(1, 1);
    load_stage(2, 2);

    int stg = 0;
    for (int kc = 0; kc < NK; kc++) {
        int rem = NK - 1 - kc;
        if (rem >= 2)      asm volatile("cp.async.wait_group 2;" ::: "memory");
        else if (rem == 1) asm volatile("cp.async.wait_group 1;" ::: "memory");
        else               asm volatile("cp.async.wait_group 0;" ::: "memory");
        __syncthreads();

        if (kc + 3 < NK) {
            int nstg = stg + 3; if (nstg >= NSTG) nstg -= NSTG;
            load_stage(kc + 3, nstg);
        }

        const uint32_t abase = sb + stg * STG;
        const uint32_t bbase = abase + ASTG;
        #pragma unroll
        for (int ks = 0; ks < 2; ks++) {
            uint32_t ah[2][4], bf2[4][2];
            const int arow = lane & 15, acoll = ks * 16 + (lane >> 4) * 8;
            const int brow = (lane & 7) + ((lane >> 4) << 3);
            const int bcol = ks * 16 + ((lane >> 3) & 1) * 8;
            #pragma unroll
            for (int ni2 = 0; ni2 < 2; ni2++) {
                // PHASE 1: ni2=0 -> filter rows wn*16.., ni2=1 -> gate rows 64+wn*16..
                // PHASE 2: contiguous 32-row warp tile.
                int nbase = (PHASE == 1) ? (ni2 * 64 + wn * 16) : (wn * 32 + ni2 * 16);
                uint32_t t4[4];
                ldmx4(t4, bbase + (nbase + brow) * 80 + bcol * 2);
                bf2[ni2*2][0] = t4[0]; bf2[ni2*2][1] = t4[1];
                bf2[ni2*2+1][0] = t4[2]; bf2[ni2*2+1][1] = t4[3];
            }
            #pragma unroll
            for (int mi = 0; mi < 2; mi++)
                ldmx4(ah[mi], abase + (wm * 32 + mi * 16 + arow) * 80 + acoll * 2);
            #pragma unroll
            for (int mi = 0; mi < 2; mi++)
                #pragma unroll
                for (int ni = 0; ni < 4; ni++)
                    mma_h(acc[mi][ni], ah[mi], bf2[ni]);
        }
        stg++; if (stg >= NSTG) stg = 0;
    }

    if (PHASE == 1) {
        // ---- in-register f/g pairing: acc[mi][ni] = f, acc[mi][ni+2] = g ----
        const int r0 = t0 + wm * 32 + (lane >> 2);
        float bfv[2][2], bgv[2][2];
        #pragma unroll
        for (int ni = 0; ni < 2; ni++) {
            int c = nb * 64 + wn * 16 + ni * 8 + (lane & 3) * 2;
            bfv[ni][0] = __ldg(b0v + c); bfv[ni][1] = __ldg(b0v + c + 1);
            bgv[ni][0] = __ldg(b1v + c); bgv[ni][1] = __ldg(b1v + c + 1);
        }
        #pragma unroll
        for (int mi = 0; mi < 2; mi++)
            #pragma unroll
            for (int ni = 0; ni < 2; ni++) {
                int c = nb * 64 + wn * 16 + ni * 8 + (lane & 3) * 2;
                #pragma unroll
                for (int h = 0; h < 2; h++) {   // h=0: row r0, h=1: row r0+8
                    float f0 = acc[mi][ni][h*2]     + bfv[ni][0];
                    float f1 = acc[mi][ni][h*2 + 1] + bfv[ni][1];
                    float g0 = acc[mi][ni+2][h*2]     + bgv[ni][0];
                    float g1 = acc[mi][ni+2][h*2 + 1] + bgv[ni][1];
                    __half h0 = __float2half_rn(gatedact(f0, g0));
                    __half h1 = __float2half_rn(gatedact(f1, g1));
                    size_t go = ((size_t)(b * TDIM + r0 + mi * 16 + h * 8)) * CHN + c;
                    *(uint32_t*)(g_z + go) =
                        ((uint32_t)__half_as_ushort(h1) << 16) | __half_as_ushort(h0);
                }
            }
    } else {
        __syncthreads();
        // ---- stage C through smem [128 n][68 m] for t-major output ----
        float* Cs = (float*)smraw;
        {
            const int tr = lane >> 2, tc4 = (lane & 3) * 2;
            #pragma unroll
            for (int mi = 0; mi < 2; mi++)
                #pragma unroll
                for (int ni = 0; ni < 4; ni++) {
                    int n0 = wn * 32 + ni * 8 + tc4;
                    int m0 = wm * 32 + mi * 16 + tr;
                    Cs[n0 * 68 + m0]           = acc[mi][ni][0];
                    Cs[(n0 + 1) * 68 + m0]     = acc[mi][ni][1];
                    Cs[n0 * 68 + m0 + 8]       = acc[mi][ni][2];
                    Cs[(n0 + 1) * 68 + m0 + 8] = acc[mi][ni][3];
                }
        }
        __syncthreads();
        for (int i = tid; i < 128 * 16; i += 256) {
            int c1 = i >> 4, mp = (i & 15) * 4;
            size_t go = ((size_t)(b * CHN + nb * 64 + ((c1 < 64) ? c1 : c1 - 64))) * TDIM + t0 + mp;
            if (c1 < 64) {
                float bias = __ldg(b0v + nb * 64 + c1);
                float4 xv = *(const float4*)(x + go);
                float4 v = make_float4(Cs[c1*68+mp]   + bias + xv.x,
                                       Cs[c1*68+mp+1] + bias + xv.y,
                                       Cs[c1*68+mp+2] + bias + xv.z,
                                       Cs[c1*68+mp+3] + bias + xv.w);
                *(float4*)(out + go) = v;
            } else {
                float bias = __ldg(b1v + nb * 64 + (c1 - 64));
                float4 v = make_float4(Cs[c1*68+mp]   + bias,
                                       Cs[c1*68+mp+1] + bias,
                                       Cs[c1*68+mp+2] + bias,
                                       Cs[c1*68+mp+3] + bias);
                *(float4*)(out + SKIPOFF + go) = v;
            }
        }
    }
}

// ---------------------------------------------------------------------------
extern "C" void kernel_launch(void* const* d_in, const int* in_sizes, int n_in,
                              void* d_out, int out_size)
{
    const float* x   = (const float*)d_in[0];
    const float* wf  = (const float*)d_in[1];
    const float* bf  = (const float*)d_in[2];
    const float* wg  = (const float*)d_in[3];
    const float* bg  = (const float*)d_in[4];
    const float* wr  = (const float*)d_in[5];
    const float* br  = (const float*)d_in[6];
    const float* wsk = (const float*)d_in[7];
    const float* bsk = (const float*)d_in[8];
    float* out = (float*)d_out;

    cudaFuncSetAttribute(gemm_tc<1>, cudaFuncAttributeMaxDynamicSharedMemorySize, SMEM_SZ);
    cudaFuncSetAttribute(gemm_tc<2>, cudaFuncAttributeMaxDynamicSharedMemorySize, SMEM_SZ);

    pack_w_kernel<<<1536, 256>>>(wf, wg, wr, wsk);
    pack_x_kernel<<<dim3(64, 4, BATCH), 256>>>(x);
    dim3 grid(64, 4, BATCH);
    gemm_tc<1><<<grid, 256, SMEM_SZ>>>(x, bf, bg, out);
    gemm_tc<2><<<grid, 256, SMEM_SZ>>>(x, br, bsk, out);
}